// round 1
// baseline (speedup 1.0000x reference)
#include <cuda_runtime.h>
#include <math.h>

#define Bv   8
#define Nv   2000
#define Cv   91
#define FG   90
#define NIMG (Nv*FG)      /* 180000 candidates per image */
#define TOPK 2048
#define DETS 100
#define EQCAP 6144
#define REGW (Cv*4)       /* 364 floats per proposal row */

__device__ float g_scores[Bv*NIMG];             // masked scores (valid ? score : -1)
__device__ unsigned long long g_keys[Bv*TOPK];  // sorted (score<<32 | ~idx) per image

// ---------- order-preserving float<->uint ----------
__device__ __forceinline__ unsigned orderf(float f) {
    unsigned u = __float_as_uint(f);
    return (u & 0x80000000u) ? ~u : (u | 0x80000000u);
}
__device__ __forceinline__ float unorderf(unsigned u) {
    u = (u & 0x80000000u) ? (u ^ 0x80000000u) : ~u;
    return __uint_as_float(u);
}

struct Box { float x1, y1, x2, y2; };

// Replicates the JAX decode + clip exactly (fp32 op sequence).
__device__ __forceinline__ Box decode_one(float4 r, float x1, float y1, float x2, float y2) {
    const float CLIPV = 4.135166556742356f;   // log(1000/16) as f32
    float w  = x2 - x1, h = y2 - y1;
    float cx = x1 + 0.5f * w, cy = y1 + 0.5f * h;
    float dx = r.x / 10.0f, dy = r.y / 10.0f;
    float dw = fminf(r.z / 5.0f, CLIPV);
    float dh = fminf(r.w / 5.0f, CLIPV);
    float pcx = dx * w + cx, pcy = dy * h + cy;
    float pw  = expf(dw) * w, ph = expf(dh) * h;
    Box o;
    o.x1 = pcx - 0.5f * pw; o.y1 = pcy - 0.5f * ph;
    o.x2 = pcx + 0.5f * pw; o.y2 = pcy + 0.5f * ph;
    o.x1 = fminf(fmaxf(o.x1, 0.0f), 1333.0f);
    o.y1 = fminf(fmaxf(o.y1, 0.0f),  800.0f);
    o.x2 = fminf(fmaxf(o.x2, 0.0f), 1333.0f);
    o.y2 = fminf(fmaxf(o.y2, 0.0f),  800.0f);
    return o;
}

// =====================================================================
// K1: one warp per proposal. Softmax over 91 classes, decode 90 fg
// boxes, write masked score to g_scores.
// =====================================================================
__global__ void score_kernel(const float* __restrict__ logits,
                             const float* __restrict__ reg,
                             const float* __restrict__ props) {
    int warp = (blockIdx.x * blockDim.x + threadIdx.x) >> 5;
    int lane = threadIdx.x & 31;
    if (warp >= Bv * Nv) return;

    const float* lrow = logits + (size_t)warp * Cv;
    float l0 = lrow[lane];
    float l1 = lrow[32 + lane];
    float l2 = (64 + lane < Cv) ? lrow[64 + lane] : -3.402823466e38f;
    float m = fmaxf(l0, fmaxf(l1, l2));
    #pragma unroll
    for (int o = 16; o; o >>= 1) m = fmaxf(m, __shfl_xor_sync(0xFFFFFFFFu, m, o));
    float s = expf(l0 - m) + expf(l1 - m) + ((64 + lane < Cv) ? expf(l2 - m) : 0.0f);
    #pragma unroll
    for (int o = 16; o; o >>= 1) s += __shfl_xor_sync(0xFFFFFFFFu, s, o);

    int b = warp / Nv, p = warp % Nv;
    const float* pb = props + (size_t)warp * 4;
    float px1 = pb[0], py1 = pb[1], px2 = pb[2], py2 = pb[3];

    float* outsc = g_scores + (size_t)b * NIMG + (size_t)p * FG;
    const float* rrow = reg + (size_t)warp * REGW;

    #pragma unroll
    for (int k = 0; k < 3; k++) {
        int c = 1 + lane + 32 * k;
        if (c <= FG) {
            float sc = expf(lrow[c] - m) / s;
            float4 r = *reinterpret_cast<const float4*>(rrow + c * 4);
            Box bx = decode_one(r, px1, py1, px2, py2);
            float ws = bx.x2 - bx.x1, hs = bx.y2 - bx.y1;
            bool valid = (sc > 0.05f) && (ws >= 0.01f) && (hs >= 0.01f);
            outsc[c - 1] = valid ? sc : -1.0f;
        }
    }
}

// =====================================================================
// K2: one block per image. Exact top-2048 via 4x8-bit radix select on
// ordered keys, tie-break by ascending flat index (JAX top_k semantics),
// then bitonic sort of 2048 (score, ~idx) 64-bit keys descending.
// =====================================================================
__global__ void __launch_bounds__(1024, 1) select_kernel() {
    int b   = blockIdx.x;
    int tid = threadIdx.x;
    const float* sc = g_scores + (size_t)b * NIMG;

    __shared__ unsigned int hist[256];
    __shared__ unsigned long long keys[TOPK];
    __shared__ unsigned int eqbuf[EQCAP];
    __shared__ unsigned int sh_prefix, sh_k, cnt_g, cnt_e;

    if (tid == 0) { sh_prefix = 0; sh_k = TOPK; }
    __syncthreads();

    // ---- radix select: find ordered-uint value of the 2048th largest ----
    for (int level = 3; level >= 0; level--) {
        int shift = level * 8;
        for (int i = tid; i < 256; i += 1024) hist[i] = 0;
        __syncthreads();
        unsigned pref = sh_prefix;
        for (int i = tid; i < NIMG; i += 1024) {
            unsigned u = orderf(sc[i]);
            bool match = (shift == 24) || ((u >> (shift + 8)) == pref);
            if (match) atomicAdd(&hist[(u >> shift) & 0xFFu], 1u);
        }
        __syncthreads();
        if (tid == 0) {
            unsigned k = sh_k, cum = 0;
            int bin = 255;
            for (; bin >= 0; bin--) {
                unsigned c = hist[bin];
                if (cum + c >= k) break;
                cum += c;
            }
            sh_prefix = (sh_prefix << 8) | (unsigned)bin;
            sh_k = k - cum;
        }
        __syncthreads();
    }
    unsigned Tu = sh_prefix;          // exact ordered value of 2048th largest
    // sh_k = number of elements == Tu to take (smallest indices first)

    if (tid == 0) { cnt_g = 0; cnt_e = 0; }
    for (int i = tid; i < TOPK; i += 1024) keys[i] = 0ull;
    __syncthreads();

    // ---- gather strictly-greater (unordered) and equals (for ranking) ----
    for (int i = tid; i < NIMG; i += 1024) {
        unsigned u = orderf(sc[i]);
        if (u > Tu) {
            unsigned pos = atomicAdd(&cnt_g, 1u);
            keys[pos] = ((unsigned long long)u << 32) | (unsigned long long)(0xFFFFFFFFu - (unsigned)i);
        } else if (u == Tu) {
            unsigned pos = atomicAdd(&cnt_e, 1u);
            if (pos < EQCAP) eqbuf[pos] = (unsigned)i;
        }
    }
    __syncthreads();

    unsigned G  = cnt_g;              // == TOPK - E
    unsigned E  = TOPK - G;
    unsigned ec = min(cnt_e, (unsigned)EQCAP);

    // rank equals by ascending index; take the first E
    for (unsigned e = tid; e < ec; e += 1024) {
        unsigned idx = eqbuf[e], rank = 0;
        for (unsigned f = 0; f < ec; f++) rank += (eqbuf[f] < idx) ? 1u : 0u;
        if (rank < E)
            keys[G + rank] = ((unsigned long long)Tu << 32) | (unsigned long long)(0xFFFFFFFFu - idx);
    }
    __syncthreads();

    // ---- bitonic sort 2048 keys descending ----
    for (unsigned kk = 2; kk <= TOPK; kk <<= 1) {
        for (unsigned j = kk >> 1; j > 0; j >>= 1) {
            __syncthreads();
            for (unsigned i = tid; i < TOPK; i += 1024) {
                unsigned p = i ^ j;
                if (p > i) {
                    bool desc = ((i & kk) == 0);
                    unsigned long long a = keys[i], c = keys[p];
                    if (desc ? (a < c) : (a > c)) { keys[i] = c; keys[p] = a; }
                }
            }
        }
    }
    __syncthreads();

    for (int i = tid; i < TOPK; i += 1024) g_keys[(size_t)b * TOPK + i] = keys[i];
}

// =====================================================================
// K3: one block per image. Re-decode 2048 candidates, class-offset
// greedy NMS in sorted order (exact JAX fp32 op sequence), emit top-100.
// =====================================================================
__global__ void __launch_bounds__(1024, 1) post_kernel(const float* __restrict__ reg,
                                                       const float* __restrict__ props,
                                                       float* __restrict__ out) {
    int b   = blockIdx.x;
    int tid = threadIdx.x;

    extern __shared__ float smem[];
    float* sb   = smem;                  // [TOPK*4] clipped boxes
    float* soff = sb   + TOPK * 4;       // [TOPK] class offsets
    float* ssc  = soff + TOPK;           // [TOPK] scores (masked)
    int*   slab = (int*)(ssc  + TOPK);   // [TOPK] labels
    int*   skp  = slab + TOPK;           // [TOPK] keep flags
    int*   spre = skp  + TOPK;           // [TOPK] exclusive keep prefix
    float* sred = (float*)(spre + TOPK); // [33] reduce scratch

    float lmax = -3.402823466e38f;
    for (int r = tid; r < TOPK; r += 1024) {
        unsigned long long key = g_keys[(size_t)b * TOPK + r];
        unsigned idx = 0xFFFFFFFFu - (unsigned)(key & 0xFFFFFFFFull);
        float score  = unorderf((unsigned)(key >> 32));
        int p = idx / FG, cls = (int)(idx % FG) + 1;
        const float* pb = props + ((size_t)b * Nv + p) * 4;
        float4 rr = *reinterpret_cast<const float4*>(reg + ((size_t)b * Nv + p) * REGW + cls * 4);
        Box bx = decode_one(rr, pb[0], pb[1], pb[2], pb[3]);
        sb[r * 4 + 0] = bx.x1; sb[r * 4 + 1] = bx.y1;
        sb[r * 4 + 2] = bx.x2; sb[r * 4 + 3] = bx.y2;
        ssc[r]  = score;
        slab[r] = cls;
        skp[r]  = (score > 0.0f) ? 1 : 0;    // valid <=> masked score > 0
        lmax = fmaxf(lmax, fmaxf(fmaxf(bx.x1, bx.y1), fmaxf(bx.x2, bx.y2)));
    }
    // block max reduce -> m
    #pragma unroll
    for (int o = 16; o; o >>= 1) lmax = fmaxf(lmax, __shfl_xor_sync(0xFFFFFFFFu, lmax, o));
    if ((tid & 31) == 0) sred[tid >> 5] = lmax;
    __syncthreads();
    if (tid < 32) {
        float v = (tid < (1024 / 32)) ? sred[tid] : -3.402823466e38f;
        #pragma unroll
        for (int o = 16; o; o >>= 1) v = fmaxf(v, __shfl_xor_sync(0xFFFFFFFFu, v, o));
        if (tid == 0) sred[32] = v;
    }
    __syncthreads();
    float m = sred[32];
    float step = m + 1.0f;
    for (int r = tid; r < TOPK; r += 1024)
        soff[r] = (float)slab[r] * step;
    __syncthreads();

    // ---- greedy NMS in score order ----
    for (int i = 0; i < TOPK; i++) {
        __syncthreads();
        if (!skp[i]) continue;
        float oi  = soff[i];
        float ax1 = sb[i * 4 + 0] + oi, ay1 = sb[i * 4 + 1] + oi;
        float ax2 = sb[i * 4 + 2] + oi, ay2 = sb[i * 4 + 3] + oi;
        float aar = (ax2 - ax1) * (ay2 - ay1);
        int   li  = slab[i];
        for (int j = i + 1 + tid; j < TOPK; j += 1024) {
            if (!skp[j] || slab[j] != li) continue;
            float oj  = soff[j];
            float bx1 = sb[j * 4 + 0] + oj, by1 = sb[j * 4 + 1] + oj;
            float bx2 = sb[j * 4 + 2] + oj, by2 = sb[j * 4 + 3] + oj;
            float bar = (bx2 - bx1) * (by2 - by1);
            float ltx = fmaxf(ax1, bx1), lty = fmaxf(ay1, by1);
            float rbx = fminf(ax2, bx2), rby = fminf(ay2, by2);
            float ww  = fmaxf(rbx - ltx, 0.0f), hh = fmaxf(rby - lty, 0.0f);
            float inter = ww * hh;
            float iou = inter / ((aar + bar) - inter);
            if (iou > 0.5f) skp[j] = 0;
        }
    }
    __syncthreads();

    // ---- emit: kept candidates in order first, then non-kept (idx asc) as -1 fill ----
    if (tid == 0) {
        int c = 0;
        for (int r = 0; r < TOPK; r++) { spre[r] = c; c += skp[r]; }
        sred[0] = __int_as_float(c);   // total kept
    }
    __syncthreads();
    int total = __float_as_int(sred[0]);

    float* oboxes  = out;                          // [B,100,4]
    float* oscores = out + Bv * DETS * 4;          // [B,100]
    float* olabels = out + Bv * DETS * 5;          // [B,100]
    for (int r = tid; r < TOPK; r += 1024) {
        int kr   = spre[r];
        int slot = skp[r] ? kr : (total + (r - kr));
        if (slot < DETS) {
            float* ob = oboxes + ((size_t)b * DETS + slot) * 4;
            ob[0] = sb[r * 4 + 0]; ob[1] = sb[r * 4 + 1];
            ob[2] = sb[r * 4 + 2]; ob[3] = sb[r * 4 + 3];
            oscores[b * DETS + slot] = skp[r] ? ssc[r] : -1.0f;
            olabels[b * DETS + slot] = (float)slab[r];
        }
    }
}

extern "C" void kernel_launch(void* const* d_in, const int* in_sizes, int n_in,
                              void* d_out, int out_size) {
    const float* logits = (const float*)d_in[0];   // [16000, 91]
    const float* reg    = (const float*)d_in[1];   // [16000, 364]
    const float* props  = (const float*)d_in[2];   // [8, 2000, 4]
    float* out = (float*)d_out;

    // K1: 16000 warps, 8 warps/block
    score_kernel<<<(Bv * Nv + 7) / 8, 256>>>(logits, reg, props);
    // K2: one block per image
    select_kernel<<<Bv, 1024>>>();
    // K3: one block per image, dynamic smem
    size_t sm = (size_t)(TOPK * 4 + TOPK + TOPK) * sizeof(float)
              + (size_t)(TOPK * 3) * sizeof(int) + 40 * sizeof(float);
    cudaFuncSetAttribute(post_kernel, cudaFuncAttributeMaxDynamicSharedMemorySize, (int)sm);
    post_kernel<<<Bv, 1024, sm>>>(reg, props, out);
}

// round 2
// speedup vs baseline: 2.8835x; 2.8835x over previous
#include <cuda_runtime.h>
#include <math.h>

#define Bv   8
#define Nv   2000
#define Cv   91
#define FG   90
#define NIMG (Nv*FG)      /* 180000 candidates per image */
#define TOPK 2048
#define DETS 100
#define EQCAP 6144
#define REGW (Cv*4)       /* 364 floats per proposal row */
#define NWORDS 32         /* 2048/64 */

__device__ float g_scores[Bv*NIMG];             // masked scores (valid ? score : -1)
__device__ unsigned long long g_keys[Bv*TOPK];  // sorted (score<<32 | ~idx) per image
__device__ float4 g_cbox[Bv*TOPK];              // clipped boxes
__device__ float4 g_obox[Bv*TOPK];              // offset boxes
__device__ float  g_cscore[Bv*TOPK];
__device__ int    g_clabel[Bv*TOPK];
__device__ unsigned long long g_valid[Bv*NWORDS];
__device__ unsigned long long g_mask[Bv*TOPK*NWORDS];   // 4 MB suppression matrix

// ---------- order-preserving float<->uint ----------
__device__ __forceinline__ unsigned orderf(float f) {
    unsigned u = __float_as_uint(f);
    return (u & 0x80000000u) ? ~u : (u | 0x80000000u);
}
__device__ __forceinline__ float unorderf(unsigned u) {
    u = (u & 0x80000000u) ? (u ^ 0x80000000u) : ~u;
    return __uint_as_float(u);
}

struct Box { float x1, y1, x2, y2; };

// Replicates the JAX decode + clip exactly (fp32 op sequence).
__device__ __forceinline__ Box decode_one(float4 r, float x1, float y1, float x2, float y2) {
    const float CLIPV = 4.135166556742356f;   // log(1000/16) as f32
    float w  = x2 - x1, h = y2 - y1;
    float cx = x1 + 0.5f * w, cy = y1 + 0.5f * h;
    float dx = r.x / 10.0f, dy = r.y / 10.0f;
    float dw = fminf(r.z / 5.0f, CLIPV);
    float dh = fminf(r.w / 5.0f, CLIPV);
    float pcx = dx * w + cx, pcy = dy * h + cy;
    float pw  = expf(dw) * w, ph = expf(dh) * h;
    Box o;
    o.x1 = pcx - 0.5f * pw; o.y1 = pcy - 0.5f * ph;
    o.x2 = pcx + 0.5f * pw; o.y2 = pcy + 0.5f * ph;
    o.x1 = fminf(fmaxf(o.x1, 0.0f), 1333.0f);
    o.y1 = fminf(fmaxf(o.y1, 0.0f),  800.0f);
    o.x2 = fminf(fmaxf(o.x2, 0.0f), 1333.0f);
    o.y2 = fminf(fmaxf(o.y2, 0.0f),  800.0f);
    return o;
}

// =====================================================================
// K1: one warp per proposal. Softmax over 91 classes, decode 90 fg
// boxes, write masked score to g_scores.
// =====================================================================
__global__ void score_kernel(const float* __restrict__ logits,
                             const float* __restrict__ reg,
                             const float* __restrict__ props) {
    int warp = (blockIdx.x * blockDim.x + threadIdx.x) >> 5;
    int lane = threadIdx.x & 31;
    if (warp >= Bv * Nv) return;

    const float* lrow = logits + (size_t)warp * Cv;
    float l0 = lrow[lane];
    float l1 = lrow[32 + lane];
    float l2 = (64 + lane < Cv) ? lrow[64 + lane] : -3.402823466e38f;
    float m = fmaxf(l0, fmaxf(l1, l2));
    #pragma unroll
    for (int o = 16; o; o >>= 1) m = fmaxf(m, __shfl_xor_sync(0xFFFFFFFFu, m, o));
    float s = expf(l0 - m) + expf(l1 - m) + ((64 + lane < Cv) ? expf(l2 - m) : 0.0f);
    #pragma unroll
    for (int o = 16; o; o >>= 1) s += __shfl_xor_sync(0xFFFFFFFFu, s, o);

    int b = warp / Nv, p = warp % Nv;
    const float* pb = props + (size_t)warp * 4;
    float px1 = pb[0], py1 = pb[1], px2 = pb[2], py2 = pb[3];

    float* outsc = g_scores + (size_t)b * NIMG + (size_t)p * FG;
    const float* rrow = reg + (size_t)warp * REGW;

    #pragma unroll
    for (int k = 0; k < 3; k++) {
        int c = 1 + lane + 32 * k;
        if (c <= FG) {
            float sc = expf(lrow[c] - m) / s;
            float4 r = *reinterpret_cast<const float4*>(rrow + c * 4);
            Box bx = decode_one(r, px1, py1, px2, py2);
            float ws = bx.x2 - bx.x1, hs = bx.y2 - bx.y1;
            bool valid = (sc > 0.05f) && (ws >= 0.01f) && (hs >= 0.01f);
            outsc[c - 1] = valid ? sc : -1.0f;
        }
    }
}

// =====================================================================
// K2: one block per image. Exact top-2048 via 4x8-bit radix select,
// tie-break ascending flat index, then bitonic sort 2048 64-bit keys.
// =====================================================================
__global__ void __launch_bounds__(1024, 1) select_kernel() {
    int b   = blockIdx.x;
    int tid = threadIdx.x;
    const float* sc = g_scores + (size_t)b * NIMG;

    __shared__ unsigned int hist[256];
    __shared__ unsigned long long keys[TOPK];
    __shared__ unsigned int eqbuf[EQCAP];
    __shared__ unsigned int sh_prefix, sh_k, cnt_g, cnt_e;

    if (tid == 0) { sh_prefix = 0; sh_k = TOPK; }
    __syncthreads();

    for (int level = 3; level >= 0; level--) {
        int shift = level * 8;
        for (int i = tid; i < 256; i += 1024) hist[i] = 0;
        __syncthreads();
        unsigned pref = sh_prefix;
        for (int i = tid; i < NIMG; i += 1024) {
            unsigned u = orderf(sc[i]);
            bool match = (shift == 24) || ((u >> (shift + 8)) == pref);
            if (match) atomicAdd(&hist[(u >> shift) & 0xFFu], 1u);
        }
        __syncthreads();
        if (tid == 0) {
            unsigned k = sh_k, cum = 0;
            int bin = 255;
            for (; bin >= 0; bin--) {
                unsigned c = hist[bin];
                if (cum + c >= k) break;
                cum += c;
            }
            sh_prefix = (sh_prefix << 8) | (unsigned)bin;
            sh_k = k - cum;
        }
        __syncthreads();
    }
    unsigned Tu = sh_prefix;

    if (tid == 0) { cnt_g = 0; cnt_e = 0; }
    for (int i = tid; i < TOPK; i += 1024) keys[i] = 0ull;
    __syncthreads();

    for (int i = tid; i < NIMG; i += 1024) {
        unsigned u = orderf(sc[i]);
        if (u > Tu) {
            unsigned pos = atomicAdd(&cnt_g, 1u);
            keys[pos] = ((unsigned long long)u << 32) | (unsigned long long)(0xFFFFFFFFu - (unsigned)i);
        } else if (u == Tu) {
            unsigned pos = atomicAdd(&cnt_e, 1u);
            if (pos < EQCAP) eqbuf[pos] = (unsigned)i;
        }
    }
    __syncthreads();

    unsigned G  = cnt_g;
    unsigned E  = TOPK - G;
    unsigned ec = min(cnt_e, (unsigned)EQCAP);

    for (unsigned e = tid; e < ec; e += 1024) {
        unsigned idx = eqbuf[e], rank = 0;
        for (unsigned f = 0; f < ec; f++) rank += (eqbuf[f] < idx) ? 1u : 0u;
        if (rank < E)
            keys[G + rank] = ((unsigned long long)Tu << 32) | (unsigned long long)(0xFFFFFFFFu - idx);
    }
    __syncthreads();

    for (unsigned kk = 2; kk <= TOPK; kk <<= 1) {
        for (unsigned j = kk >> 1; j > 0; j >>= 1) {
            __syncthreads();
            for (unsigned i = tid; i < TOPK; i += 1024) {
                unsigned p = i ^ j;
                if (p > i) {
                    bool desc = ((i & kk) == 0);
                    unsigned long long a = keys[i], c = keys[p];
                    if (desc ? (a < c) : (a > c)) { keys[i] = c; keys[p] = a; }
                }
            }
        }
    }
    __syncthreads();

    for (int i = tid; i < TOPK; i += 1024) g_keys[(size_t)b * TOPK + i] = keys[i];
}

// =====================================================================
// K3a: one block per image. Decode candidates, class offsets, valid
// bitmask; stage everything to gmem for the mask/reduce kernels.
// =====================================================================
__global__ void __launch_bounds__(1024, 1) prep_kernel(const float* __restrict__ reg,
                                                       const float* __restrict__ props) {
    __shared__ float4 sbox[TOPK];
    __shared__ int    slab[TOPK];
    __shared__ float  sred[33];
    __shared__ unsigned long long svalid[NWORDS];

    int b   = blockIdx.x;
    int tid = threadIdx.x;
    if (tid < NWORDS) svalid[tid] = 0ull;
    __syncthreads();

    float lmax = -3.402823466e38f;
    for (int r = tid; r < TOPK; r += 1024) {
        unsigned long long key = g_keys[(size_t)b * TOPK + r];
        unsigned idx = 0xFFFFFFFFu - (unsigned)(key & 0xFFFFFFFFull);
        float score  = unorderf((unsigned)(key >> 32));
        int p = idx / FG, cls = (int)(idx % FG) + 1;
        const float* pb = props + ((size_t)b * Nv + p) * 4;
        float4 rr = *reinterpret_cast<const float4*>(reg + ((size_t)b * Nv + p) * REGW + cls * 4);
        Box bx = decode_one(rr, pb[0], pb[1], pb[2], pb[3]);
        sbox[r] = make_float4(bx.x1, bx.y1, bx.x2, bx.y2);
        slab[r] = cls;
        g_cscore[(size_t)b * TOPK + r] = score;
        if (score > 0.0f)
            atomicOr(&svalid[r >> 6], 1ull << (r & 63));
        lmax = fmaxf(lmax, fmaxf(fmaxf(bx.x1, bx.y1), fmaxf(bx.x2, bx.y2)));
    }
    #pragma unroll
    for (int o = 16; o; o >>= 1) lmax = fmaxf(lmax, __shfl_xor_sync(0xFFFFFFFFu, lmax, o));
    if ((tid & 31) == 0) sred[tid >> 5] = lmax;
    __syncthreads();
    if (tid < 32) {
        float v = sred[tid];
        #pragma unroll
        for (int o = 16; o; o >>= 1) v = fmaxf(v, __shfl_xor_sync(0xFFFFFFFFu, v, o));
        if (tid == 0) sred[32] = v;
    }
    __syncthreads();
    float step = sred[32] + 1.0f;

    for (int r = tid; r < TOPK; r += 1024) {
        float off = (float)slab[r] * step;
        float4 cb = sbox[r];
        g_cbox[(size_t)b * TOPK + r]   = cb;
        g_obox[(size_t)b * TOPK + r]   = make_float4(cb.x + off, cb.y + off, cb.z + off, cb.w + off);
        g_clabel[(size_t)b * TOPK + r] = slab[r];
    }
    if (tid < NWORDS) g_valid[b * NWORDS + tid] = svalid[tid];
}

// =====================================================================
// K3b: suppression bitmask. Grid = Bv*32 blocks (64-row tiles), 256 thr.
// Thread = (word w, rowgroup of 8). bit(i,j) = iou>0.5 && j>i, fp op
// sequence identical to the previously-passing serial version.
// =====================================================================
__global__ void __launch_bounds__(256, 4) mask_kernel() {
    __shared__ float4 ob[TOPK];      // 32KB offset boxes
    __shared__ float  ar[TOPK];      // 8KB areas

    int b    = blockIdx.x / 32;
    int tile = blockIdx.x % 32;
    int tid  = threadIdx.x;

    for (int i = tid; i < TOPK; i += 256) {
        float4 v = g_obox[(size_t)b * TOPK + i];
        ob[i] = v;
        ar[i] = (v.z - v.x) * (v.w - v.y);
    }
    __syncthreads();

    int w  = tid & 31;
    int rg = tid >> 5;
    int rowbase = tile * 64 + rg * 8;

    unsigned long long acc[8];
    #pragma unroll
    for (int r = 0; r < 8; r++) acc[r] = 0ull;

    if (w * 64 + 63 > rowbase) {   // some j > i possible in this word
        float4 rb[8]; float raar[8];
        #pragma unroll
        for (int r = 0; r < 8; r++) { rb[r] = ob[rowbase + r]; raar[r] = ar[rowbase + r]; }
        for (int jj = 0; jj < 64; jj++) {
            int j = w * 64 + jj;
            float4 bj = ob[j];
            float bar = ar[j];
            #pragma unroll
            for (int r = 0; r < 8; r++) {
                int i = rowbase + r;
                float ltx = fmaxf(rb[r].x, bj.x), lty = fmaxf(rb[r].y, bj.y);
                float rbx = fminf(rb[r].z, bj.z), rby = fminf(rb[r].w, bj.w);
                float ww  = fmaxf(rbx - ltx, 0.0f), hh = fmaxf(rby - lty, 0.0f);
                float inter = ww * hh;
                float iou = inter / ((raar[r] + bar) - inter);
                if ((j > i) && (iou > 0.5f)) acc[r] |= (1ull << jj);
            }
        }
    }
    #pragma unroll
    for (int r = 0; r < 8; r++)
        g_mask[((size_t)b * TOPK + rowbase + r) * NWORDS + w] = acc[r];
}

// =====================================================================
// K3c: serial reduce (one warp per image) + emission of top-100.
// keep_i = valid_i & !supp_i ; supp |= keep_i ? M[i] : 0 — identical
// to the greedy loop. Double-buffered 16-row prefetch hides L2 latency.
// =====================================================================
__global__ void __launch_bounds__(32, 1) reduce_emit_kernel(float* __restrict__ out) {
    int b    = blockIdx.x;
    int lane = threadIdx.x;
    const unsigned long long* mrow = g_mask + (size_t)b * TOPK * NWORDS;

    unsigned long long vw   = g_valid[b * NWORDS + lane];
    unsigned long long supp = 0ull;

    unsigned long long cur[16], nxt[16];
    #pragma unroll
    for (int k = 0; k < 16; k++) cur[k] = mrow[(size_t)k * NWORDS + lane];

    for (int base = 0; base < TOPK; base += 16) {
        int nb = base + 16;
        #pragma unroll
        for (int k = 0; k < 16; k++)
            nxt[k] = (nb + k < TOPK) ? mrow[(size_t)(nb + k) * NWORDS + lane] : 0ull;
        #pragma unroll
        for (int k = 0; k < 16; k++) {
            int i = base + k;
            int owner = i >> 6, bit = i & 63;
            unsigned my = (unsigned)((vw >> bit) & 1ull) & (unsigned)((~supp >> bit) & 1ull);
            unsigned kept = __shfl_sync(0xFFFFFFFFu, my, owner);
            if (kept) supp |= cur[k];
        }
        #pragma unroll
        for (int k = 0; k < 16; k++) cur[k] = nxt[k];
    }

    unsigned long long keep = vw & ~supp;

    // warp exclusive scan of per-word keep counts
    int cnt = __popcll(keep);
    int inc = cnt;
    #pragma unroll
    for (int o = 1; o < 32; o <<= 1) {
        int v = __shfl_up_sync(0xFFFFFFFFu, inc, o);
        if (lane >= o) inc += v;
    }
    int excl  = inc - cnt;
    int total = __shfl_sync(0xFFFFFFFFu, inc, 31);

    float* oboxes  = out;                     // [B,100,4]
    float* oscores = out + Bv * DETS * 4;     // [B,100]
    float* olabels = out + Bv * DETS * 5;     // [B,100]

    for (int k = 0; k < 64; k++) {
        int r = lane * 64 + k;
        unsigned long long below = (k == 0) ? 0ull : (keep & ((1ull << k) - 1ull));
        int kb   = excl + __popcll(below);
        int kp   = (int)((keep >> k) & 1ull);
        int slot = kp ? kb : total + (r - kb);
        if (slot < DETS) {
            float4 cb = g_cbox[(size_t)b * TOPK + r];
            float* obp = oboxes + ((size_t)b * DETS + slot) * 4;
            obp[0] = cb.x; obp[1] = cb.y; obp[2] = cb.z; obp[3] = cb.w;
            oscores[b * DETS + slot] = kp ? g_cscore[(size_t)b * TOPK + r] : -1.0f;
            olabels[b * DETS + slot] = (float)g_clabel[(size_t)b * TOPK + r];
        }
    }
}

extern "C" void kernel_launch(void* const* d_in, const int* in_sizes, int n_in,
                              void* d_out, int out_size) {
    const float* logits = (const float*)d_in[0];   // [16000, 91]
    const float* reg    = (const float*)d_in[1];   // [16000, 364]
    const float* props  = (const float*)d_in[2];   // [8, 2000, 4]
    float* out = (float*)d_out;

    score_kernel<<<(Bv * Nv + 7) / 8, 256>>>(logits, reg, props);
    select_kernel<<<Bv, 1024>>>();
    prep_kernel<<<Bv, 1024>>>(reg, props);
    mask_kernel<<<Bv * 32, 256>>>();
    reduce_emit_kernel<<<Bv, 32>>>(out);
}

// round 3
// speedup vs baseline: 3.0827x; 1.0691x over previous
#include <cuda_runtime.h>
#include <math.h>

#define Bv   8
#define Nv   2000
#define Cv   91
#define FG   90
#define NIMG (Nv*FG)      /* 180000 candidates per image */
#define TOPK 2048
#define DETS 100
#define REGW (Cv*4)       /* 364 floats per proposal row */
#define NWORDS 32         /* 2048/64 */
#define NBINS 65536
#define GCAP  16384

typedef unsigned long long u64;

__device__ float g_scores[Bv*NIMG];             // masked scores (valid ? score : -1)
__device__ unsigned g_hist[Bv*NBINS];
__device__ unsigned g_thr[Bv];
__device__ unsigned g_gcnt[Bv];
__device__ u64 g_cand[Bv*GCAP];
__device__ u64 g_keys[Bv*TOPK];                 // sorted (score<<32 | ~idx) per image
__device__ float4 g_cbox[Bv*TOPK];              // clipped boxes
__device__ float4 g_obox[Bv*TOPK];              // offset boxes
__device__ float  g_cscore[Bv*TOPK];
__device__ int    g_clabel[Bv*TOPK];
__device__ u64 g_valid[Bv*NWORDS];
__device__ u64 g_mask[Bv*TOPK*NWORDS];          // 4 MB suppression matrix

// ---------- order-preserving float<->uint ----------
__device__ __forceinline__ unsigned orderf(float f) {
    unsigned u = __float_as_uint(f);
    return (u & 0x80000000u) ? ~u : (u | 0x80000000u);
}
__device__ __forceinline__ float unorderf(unsigned u) {
    u = (u & 0x80000000u) ? (u ^ 0x80000000u) : ~u;
    return __uint_as_float(u);
}

struct Box { float x1, y1, x2, y2; };

// Replicates the JAX decode + clip exactly (fp32 op sequence).
__device__ __forceinline__ Box decode_one(float4 r, float x1, float y1, float x2, float y2) {
    const float CLIPV = 4.135166556742356f;   // log(1000/16) as f32
    float w  = x2 - x1, h = y2 - y1;
    float cx = x1 + 0.5f * w, cy = y1 + 0.5f * h;
    float dx = r.x / 10.0f, dy = r.y / 10.0f;
    float dw = fminf(r.z / 5.0f, CLIPV);
    float dh = fminf(r.w / 5.0f, CLIPV);
    float pcx = dx * w + cx, pcy = dy * h + cy;
    float pw  = expf(dw) * w, ph = expf(dh) * h;
    Box o;
    o.x1 = pcx - 0.5f * pw; o.y1 = pcy - 0.5f * ph;
    o.x2 = pcx + 0.5f * pw; o.y2 = pcy + 0.5f * ph;
    o.x1 = fminf(fmaxf(o.x1, 0.0f), 1333.0f);
    o.y1 = fminf(fmaxf(o.y1, 0.0f),  800.0f);
    o.x2 = fminf(fmaxf(o.x2, 0.0f), 1333.0f);
    o.y2 = fminf(fmaxf(o.y2, 0.0f),  800.0f);
    return o;
}

// =====================================================================
// K0: zero the histogram + gather counters (graph-replay determinism)
// =====================================================================
__global__ void zero_kernel() {
    unsigned i = blockIdx.x * 1024u + threadIdx.x;
    if (i < Bv * NBINS) g_hist[i] = 0u;
    if (i < Bv) g_gcnt[i] = 0u;
}

// =====================================================================
// K1: one warp per proposal. Softmax over 91 classes (lane owns its
// classes: c = lane + 32k), decode fg boxes, write masked score,
// histogram valid scores (top-16 ordered bits).
// =====================================================================
__global__ void score_kernel(const float* __restrict__ logits,
                             const float* __restrict__ reg,
                             const float* __restrict__ props) {
    int warp = (blockIdx.x * blockDim.x + threadIdx.x) >> 5;
    int lane = threadIdx.x & 31;
    if (warp >= Bv * Nv) return;

    const float* lrow = logits + (size_t)warp * Cv;
    float l0 = lrow[lane];
    float l1 = lrow[32 + lane];
    float l2 = (64 + lane < Cv) ? lrow[64 + lane] : -3.402823466e38f;
    float m = fmaxf(l0, fmaxf(l1, l2));
    #pragma unroll
    for (int o = 16; o; o >>= 1) m = fmaxf(m, __shfl_xor_sync(0xFFFFFFFFu, m, o));
    float e0 = expf(l0 - m), e1 = expf(l1 - m);
    float e2 = (64 + lane < Cv) ? expf(l2 - m) : 0.0f;
    float s = e0 + e1 + e2;
    #pragma unroll
    for (int o = 16; o; o >>= 1) s += __shfl_xor_sync(0xFFFFFFFFu, s, o);

    int b = warp / Nv, p = warp % Nv;
    const float* pb = props + (size_t)warp * 4;
    float px1 = pb[0], py1 = pb[1], px2 = pb[2], py2 = pb[3];

    float* outsc = g_scores + (size_t)b * NIMG + (size_t)p * FG;
    const float* rrow = reg + (size_t)warp * REGW;

    float ev[3] = {e0, e1, e2};
    #pragma unroll
    for (int k = 0; k < 3; k++) {
        int c = lane + 32 * k;
        if (c >= 1 && c <= FG) {
            float sc = ev[k] / s;
            float4 r = *reinterpret_cast<const float4*>(rrow + c * 4);
            Box bx = decode_one(r, px1, py1, px2, py2);
            float ws = bx.x2 - bx.x1, hs = bx.y2 - bx.y1;
            bool valid = (sc > 0.05f) && (ws >= 0.01f) && (hs >= 0.01f);
            float msc = valid ? sc : -1.0f;
            outsc[c - 1] = msc;
            if (valid)
                atomicAdd(&g_hist[b * NBINS + (orderf(msc) >> 16)], 1u);
        }
    }
}

// =====================================================================
// K2a: per image, find threshold bin: smallest (from top) bin with
// cumulative count >= TOPK.
// =====================================================================
__global__ void __launch_bounds__(256, 1) findthr_kernel() {
    int b = blockIdx.x, tid = threadIdx.x;
    __shared__ unsigned csum[256];
    const unsigned* h = g_hist + b * NBINS;
    unsigned sum = 0;
    int base = tid * 256;
    for (int i = 0; i < 256; i++) sum += h[base + i];
    csum[tid] = sum;
    __syncthreads();
    if (tid == 0) {
        unsigned acc = 0;
        int c = 255;
        for (; c >= 0; c--) {
            if (acc + csum[c] >= TOPK) break;
            acc += csum[c];
        }
        unsigned thr = 0;
        if (c >= 0) {
            int bin = c * 256 + 255;
            for (; bin >= c * 256; bin--) {
                acc += h[bin];
                if (acc >= TOPK) break;
            }
            thr = (unsigned)(bin >= c * 256 ? bin : c * 256);
        }
        g_thr[b] = thr;
    }
}

// =====================================================================
// K2b: gather composite keys with bin >= thr  (unique keys => exact
// tie semantics handled by the 64-bit composite ordering).
// =====================================================================
__global__ void gather_kernel() {
    int b   = blockIdx.x >> 5;
    int bi  = blockIdx.x & 31;
    int tid = threadIdx.x;
    const float* sc = g_scores + (size_t)b * NIMG;
    unsigned thr = g_thr[b];
    for (int i = bi * 256 + tid; i < NIMG; i += 32 * 256) {
        unsigned u = orderf(sc[i]);
        if ((u >> 16) >= thr) {
            unsigned pos = atomicAdd(&g_gcnt[b], 1u);
            if (pos < GCAP)
                g_cand[(size_t)b * GCAP + pos] =
                    ((u64)u << 32) | (u64)(0xFFFFFFFFu - (unsigned)i);
        }
    }
}

// =====================================================================
// K2c: per-image bitonic sort (desc) of gathered keys, emit top-2048.
// =====================================================================
__global__ void __launch_bounds__(1024, 1) sort_kernel() {
    extern __shared__ u64 skeys[];
    int b = blockIdx.x, tid = threadIdx.x;
    unsigned cnt = g_gcnt[b];
    if (cnt > GCAP) cnt = GCAP;
    unsigned P2 = 2048;
    while (P2 < cnt) P2 <<= 1;
    for (unsigned i = tid; i < P2; i += 1024)
        skeys[i] = (i < cnt) ? g_cand[(size_t)b * GCAP + i] : 0ull;
    __syncthreads();
    for (unsigned kk = 2; kk <= P2; kk <<= 1) {
        for (unsigned j = kk >> 1; j; j >>= 1) {
            for (unsigned i = tid; i < P2; i += 1024) {
                unsigned p = i ^ j;
                if (p > i) {
                    bool desc = ((i & kk) == 0);
                    u64 a = skeys[i], c = skeys[p];
                    if (desc ? (a < c) : (a > c)) { skeys[i] = c; skeys[p] = a; }
                }
            }
            __syncthreads();
        }
    }
    for (int i = tid; i < TOPK; i += 1024) g_keys[(size_t)b * TOPK + i] = skeys[i];
}

// =====================================================================
// K3a: one block per image. Decode candidates, class offsets, valid
// bitmask; stage everything to gmem for the mask/reduce kernels.
// =====================================================================
__global__ void __launch_bounds__(1024, 1) prep_kernel(const float* __restrict__ reg,
                                                       const float* __restrict__ props) {
    __shared__ float4 sbox[TOPK];
    __shared__ int    slab[TOPK];
    __shared__ float  sred[33];
    __shared__ u64    svalid[NWORDS];

    int b   = blockIdx.x;
    int tid = threadIdx.x;
    if (tid < NWORDS) svalid[tid] = 0ull;
    __syncthreads();

    float lmax = -3.402823466e38f;
    for (int r = tid; r < TOPK; r += 1024) {
        u64 key = g_keys[(size_t)b * TOPK + r];
        unsigned idx = 0xFFFFFFFFu - (unsigned)(key & 0xFFFFFFFFull);
        if (idx >= NIMG) idx = NIMG - 1;     // safety clamp (padding)
        float score  = unorderf((unsigned)(key >> 32));
        int p = idx / FG, cls = (int)(idx % FG) + 1;
        const float* pb = props + ((size_t)b * Nv + p) * 4;
        float4 rr = *reinterpret_cast<const float4*>(reg + ((size_t)b * Nv + p) * REGW + cls * 4);
        Box bx = decode_one(rr, pb[0], pb[1], pb[2], pb[3]);
        sbox[r] = make_float4(bx.x1, bx.y1, bx.x2, bx.y2);
        slab[r] = cls;
        g_cscore[(size_t)b * TOPK + r] = score;
        if (score > 0.0f)
            atomicOr(&svalid[r >> 6], 1ull << (r & 63));
        lmax = fmaxf(lmax, fmaxf(fmaxf(bx.x1, bx.y1), fmaxf(bx.x2, bx.y2)));
    }
    #pragma unroll
    for (int o = 16; o; o >>= 1) lmax = fmaxf(lmax, __shfl_xor_sync(0xFFFFFFFFu, lmax, o));
    if ((tid & 31) == 0) sred[tid >> 5] = lmax;
    __syncthreads();
    if (tid < 32) {
        float v = sred[tid];
        #pragma unroll
        for (int o = 16; o; o >>= 1) v = fmaxf(v, __shfl_xor_sync(0xFFFFFFFFu, v, o));
        if (tid == 0) sred[32] = v;
    }
    __syncthreads();
    float step = sred[32] + 1.0f;

    for (int r = tid; r < TOPK; r += 1024) {
        float off = (float)slab[r] * step;
        float4 cb = sbox[r];
        g_cbox[(size_t)b * TOPK + r]   = cb;
        g_obox[(size_t)b * TOPK + r]   = make_float4(cb.x + off, cb.y + off, cb.z + off, cb.w + off);
        g_clabel[(size_t)b * TOPK + r] = slab[r];
    }
    if (tid < NWORDS) g_valid[b * NWORDS + tid] = svalid[tid];
}

// =====================================================================
// K3b: suppression bitmask. Grid = Bv*128 blocks (16-row tiles), 256
// thr = 32 words x 8 rowgroups x 2 rows. Division replaced by a band
// test; exact div only in the ~1e-6-wide ambiguous band (bit-exact).
// Words fully below the diagonal are never written (stay zero-init).
// =====================================================================
__global__ void __launch_bounds__(256, 5) mask_kernel() {
    __shared__ float4 ob[TOPK];      // 32KB offset boxes
    __shared__ float  ar[TOPK];      // 8KB areas

    int b    = blockIdx.x >> 7;
    int tile = blockIdx.x & 127;
    int tid  = threadIdx.x;
    int rowbase = tile * 16;
    int wmin = rowbase >> 6;
    int lo   = wmin << 6;

    for (int i = lo + tid; i < TOPK; i += 256) {
        float4 v = g_obox[(size_t)b * TOPK + i];
        ob[i] = v;
        ar[i] = (v.z - v.x) * (v.w - v.y);
    }
    __syncthreads();

    int w = tid & 31;
    if (w < wmin) return;
    int r0 = rowbase + (tid >> 5) * 2;

    float4 rb0 = ob[r0],     rb1 = ob[r0 + 1];
    float  aa0 = ar[r0],     aa1 = ar[r0 + 1];
    u64 acc0 = 0ull, acc1 = 0ull;

    #pragma unroll 4
    for (int jj = 0; jj < 64; jj++) {
        int j = w * 64 + jj;
        float4 bj = ob[j];
        float bar = ar[j];
        // row 0
        {
            float ltx = fmaxf(rb0.x, bj.x), lty = fmaxf(rb0.y, bj.y);
            float rbx = fminf(rb0.z, bj.z), rby = fminf(rb0.w, bj.w);
            float ww  = fmaxf(rbx - ltx, 0.0f), hh = fmaxf(rby - lty, 0.0f);
            float inter = ww * hh;
            float U = (aa0 + bar) - inter;
            float hU = 0.5f * U;
            bool sup;
            if (inter > hU * 1.000001f)       sup = true;
            else if (inter < hU * 0.999999f)  sup = false;
            else                               sup = (inter / U) > 0.5f;
            if (sup && (j > r0)) acc0 |= (1ull << jj);
        }
        // row 1
        {
            float ltx = fmaxf(rb1.x, bj.x), lty = fmaxf(rb1.y, bj.y);
            float rbx = fminf(rb1.z, bj.z), rby = fminf(rb1.w, bj.w);
            float ww  = fmaxf(rbx - ltx, 0.0f), hh = fmaxf(rby - lty, 0.0f);
            float inter = ww * hh;
            float U = (aa1 + bar) - inter;
            float hU = 0.5f * U;
            bool sup;
            if (inter > hU * 1.000001f)       sup = true;
            else if (inter < hU * 0.999999f)  sup = false;
            else                               sup = (inter / U) > 0.5f;
            if (sup && (j > r0 + 1)) acc1 |= (1ull << jj);
        }
    }
    g_mask[((size_t)b * TOPK + r0)     * NWORDS + w] = acc0;
    g_mask[((size_t)b * TOPK + r0 + 1) * NWORDS + w] = acc1;
}

// =====================================================================
// K3c: serial reduce (one warp per image) + emission. 32-row batches
// share one owner word: owner runs local ffs loop on the keepable
// window (diag suppression folded in), one shfl broadcast, then
// independent ORs on all lanes. Double-buffered prefetch.
// =====================================================================
__global__ void __launch_bounds__(32, 1) reduce_emit_kernel(float* __restrict__ out) {
    int b    = blockIdx.x;
    int lane = threadIdx.x;
    const u64* mrow = g_mask + (size_t)b * TOPK * NWORDS;

    u64 vw   = g_valid[b * NWORDS + lane];
    u64 supp = 0ull;

    u64 cur[32], nxt[32];
    #pragma unroll
    for (int k = 0; k < 32; k++) cur[k] = mrow[(size_t)k * NWORDS + lane];

    for (int base = 0; base < TOPK; base += 32) {
        int nb = base + 32;
        if (nb < TOPK) {
            #pragma unroll
            for (int k = 0; k < 32; k++) nxt[k] = mrow[(size_t)(nb + k) * NWORDS + lane];
        }
        int owner = base >> 6;
        int shift = base & 63;      // 0 or 32
        unsigned kept32 = 0;
        if (lane == owner) {
            unsigned w32 = (unsigned)((vw & ~supp) >> shift);
            while (w32) {
                int k = __ffs(w32) - 1;
                kept32 |= (1u << k);
                u64 mk = cur[k];
                supp |= mk;
                w32 &= ~((unsigned)(mk >> shift) | (1u << k));
            }
        }
        kept32 = __shfl_sync(0xFFFFFFFFu, kept32, owner);
        u64 t0 = 0ull, t1 = 0ull;
        #pragma unroll
        for (int k = 0; k < 32; k += 2) {
            if (kept32 & (1u << k))       t0 |= cur[k];
            if (kept32 & (1u << (k + 1))) t1 |= cur[k + 1];
        }
        supp |= t0 | t1;
        #pragma unroll
        for (int k = 0; k < 32; k++) cur[k] = nxt[k];
    }

    u64 keep = vw & ~supp;

    // warp exclusive scan of per-word keep counts
    int cnt = __popcll(keep);
    int inc = cnt;
    #pragma unroll
    for (int o = 1; o < 32; o <<= 1) {
        int v = __shfl_up_sync(0xFFFFFFFFu, inc, o);
        if (lane >= o) inc += v;
    }
    int excl  = inc - cnt;
    int total = __shfl_sync(0xFFFFFFFFu, inc, 31);

    float* oboxes  = out;                     // [B,100,4]
    float* oscores = out + Bv * DETS * 4;     // [B,100]
    float* olabels = out + Bv * DETS * 5;     // [B,100]

    for (int k = 0; k < 64; k++) {
        int r = lane * 64 + k;
        u64 below = (k == 0) ? 0ull : (keep & ((1ull << k) - 1ull));
        int kb   = excl + __popcll(below);
        int kp   = (int)((keep >> k) & 1ull);
        int slot = kp ? kb : total + (r - kb);
        if (slot < DETS) {
            float4 cb = g_cbox[(size_t)b * TOPK + r];
            float* obp = oboxes + ((size_t)b * DETS + slot) * 4;
            obp[0] = cb.x; obp[1] = cb.y; obp[2] = cb.z; obp[3] = cb.w;
            oscores[b * DETS + slot] = kp ? g_cscore[(size_t)b * TOPK + r] : -1.0f;
            olabels[b * DETS + slot] = (float)g_clabel[(size_t)b * TOPK + r];
        }
    }
}

extern "C" void kernel_launch(void* const* d_in, const int* in_sizes, int n_in,
                              void* d_out, int out_size) {
    const float* logits = (const float*)d_in[0];   // [16000, 91]
    const float* reg    = (const float*)d_in[1];   // [16000, 364]
    const float* props  = (const float*)d_in[2];   // [8, 2000, 4]
    float* out = (float*)d_out;

    zero_kernel<<<(Bv * NBINS + 1023) / 1024, 1024>>>();
    score_kernel<<<(Bv * Nv + 7) / 8, 256>>>(logits, reg, props);
    findthr_kernel<<<Bv, 256>>>();
    gather_kernel<<<Bv * 32, 256>>>();
    cudaFuncSetAttribute(sort_kernel, cudaFuncAttributeMaxDynamicSharedMemorySize,
                         GCAP * (int)sizeof(u64));
    sort_kernel<<<Bv, 1024, GCAP * sizeof(u64)>>>();
    prep_kernel<<<Bv, 1024>>>(reg, props);
    mask_kernel<<<Bv * 128, 256>>>();
    reduce_emit_kernel<<<Bv, 32>>>(out);
}